// round 1
// baseline (speedup 1.0000x reference)
#include <cuda_runtime.h>
#include <cstdint>

#define N_FFT 8192
#define NT    512
#define D_CH  512
#define SEQ   4096

// Scratch (allowed: __device__ globals, no runtime allocation)
__device__ float2 g_tw[N_FFT];                 // twiddle table: exp(-2*pi*i*k/N)
__device__ float2 g_tfft[(size_t)D_CH * N_FFT]; // per-channel spectrum of t (33.5 MB)

__device__ __forceinline__ float2 cadd(float2 a, float2 b) { return make_float2(a.x + b.x, a.y + b.y); }
__device__ __forceinline__ float2 csub(float2 a, float2 b) { return make_float2(a.x - b.x, a.y - b.y); }
__device__ __forceinline__ float2 cmul(float2 a, float2 b) {
    return make_float2(a.x * b.x - a.y * b.y, a.x * b.y + a.y * b.x);
}

// multiply by -i (forward) / +i (inverse)
template <bool INV>
__device__ __forceinline__ float2 mulJ(float2 z) {
    return INV ? make_float2(-z.y, z.x) : make_float2(z.y, -z.x);
}
// multiply by w8^1 = (1-i)/sqrt2 (forward) or its conjugate (inverse)
template <bool INV>
__device__ __forceinline__ float2 mulW81(float2 z) {
    const float c = 0.70710678118654752440f;
    return INV ? make_float2(c * (z.x - z.y), c * (z.x + z.y))
               : make_float2(c * (z.x + z.y), c * (z.y - z.x));
}
// multiply by w8^3 = (-1-i)/sqrt2 (forward) or its conjugate (inverse)
template <bool INV>
__device__ __forceinline__ float2 mulW83(float2 z) {
    const float c = 0.70710678118654752440f;
    return INV ? make_float2(-c * (z.x + z.y), c * (z.x - z.y))
               : make_float2(c * (z.y - z.x), -c * (z.x + z.y));
}

// 8-point DFT, DIF ordering (outputs y[r] = sum_j a[j] * w8^{r*j})
template <bool INV>
__device__ __forceinline__ void dft8(const float2 a[8], float2 y[8]) {
    float2 b0 = cadd(a[0], a[4]), b1 = cadd(a[1], a[5]), b2 = cadd(a[2], a[6]), b3 = cadd(a[3], a[7]);
    float2 c0 = csub(a[0], a[4]), c1 = csub(a[1], a[5]), c2 = csub(a[2], a[6]), c3 = csub(a[3], a[7]);
    // even outputs: DFT4(b)
    float2 d0 = cadd(b0, b2), d1 = csub(b0, b2), d2 = cadd(b1, b3), d3 = csub(b1, b3);
    y[0] = cadd(d0, d2);
    y[4] = csub(d0, d2);
    float2 jd3 = mulJ<INV>(d3);
    y[2] = cadd(d1, jd3);
    y[6] = csub(d1, jd3);
    // odd outputs: DFT4(c_j * w8^j)
    float2 e0 = c0;
    float2 e1 = mulW81<INV>(c1);
    float2 e2 = mulJ<INV>(c2);
    float2 e3 = mulW83<INV>(c3);
    float2 f0 = cadd(e0, e2), f1 = csub(e0, e2), f2 = cadd(e1, e3), f3 = csub(e1, e3);
    y[1] = cadd(f0, f2);
    y[5] = csub(f0, f2);
    float2 jf3 = mulJ<INV>(f3);
    y[3] = cadd(f1, jf3);
    y[7] = csub(f1, jf3);
}

// One Stockham radix-8 pass. n * s = N_FFT, m = n/8. X -> Y.
template <bool INV>
__device__ __forceinline__ void pass8(const float2* __restrict__ X, float2* __restrict__ Y,
                                      int sLog, int tid) {
    const int s = 1 << sLog;
    const int m = N_FFT >> (3 + sLog);
#pragma unroll
    for (int bi = tid; bi < N_FFT / 8; bi += NT) {
        const int q = bi & (s - 1);
        const int p = bi >> sLog;
        float2 a[8];
#pragma unroll
        for (int r = 0; r < 8; r++) a[r] = X[q + s * (p + r * m)];
        float2 y[8];
        dft8<INV>(a, y);
        const int base = p << sLog;  // p * s
#pragma unroll
        for (int r = 1; r < 8; r++) {
            float2 w = g_tw[r * base];
            if (INV) w.y = -w.y;
            y[r] = cmul(y[r], w);
        }
        const int ob = q + (p << (sLog + 3));
#pragma unroll
        for (int r = 0; r < 8; r++) Y[ob + s * r] = y[r];
    }
}

// Final radix-2 pass (n=2, s=4096): no twiddles.
__device__ __forceinline__ void pass2(const float2* __restrict__ X, float2* __restrict__ Y, int tid) {
#pragma unroll
    for (int q = tid; q < N_FFT / 2; q += NT) {
        float2 a = X[q], b = X[q + N_FFT / 2];
        Y[q] = cadd(a, b);
        Y[q + N_FFT / 2] = csub(a, b);
    }
}

// Full 8192-point FFT: input in A, result ends in B. Caller syncs before entry.
template <bool INV>
__device__ __forceinline__ void fft8192(float2* A, float2* B, int tid) {
    pass8<INV>(A, B, 0, tid); __syncthreads();
    pass8<INV>(B, A, 3, tid); __syncthreads();
    pass8<INV>(A, B, 6, tid); __syncthreads();
    pass8<INV>(B, A, 9, tid); __syncthreads();
    pass2(A, B, tid);         __syncthreads();
}

// ---------------------------------------------------------------------------
__global__ void ker_tw() {
    int k = blockIdx.x * blockDim.x + threadIdx.x;
    if (k < N_FFT) {
        float s, c;
        sincospif(-2.0f * (float)k / (float)N_FFT, &s, &c);
        g_tw[k] = make_float2(c, s);
    }
}

// t spectrum: one block handles channels (2c, 2c+1) packed as real+imag of one FFT.
__global__ void __launch_bounds__(NT) ker_tfft(const float* __restrict__ t) {
    extern __shared__ float2 sm[];
    float2* A = sm;
    float2* B = sm + N_FFT;
    const int c0 = blockIdx.x;  // 0..255
    const int tid = threadIdx.x;
    const float* tp = t + 2 * c0;
    for (int m = tid; m < N_FFT; m += NT)
        A[m] = *reinterpret_cast<const float2*>(tp + (size_t)m * D_CH);
    __syncthreads();
    fft8192<false>(A, B, tid);
    // Hermitian unpack: Z = T0 + i*T1 with T0,T1 spectra of real signals.
    float2* out0 = g_tfft + (size_t)(2 * c0) * N_FFT;
    float2* out1 = g_tfft + (size_t)(2 * c0 + 1) * N_FFT;
    for (int k = tid; k < N_FFT; k += NT) {
        float2 Zk = B[k];
        float2 Zn = B[(N_FFT - k) & (N_FFT - 1)];
        out0[k] = make_float2(0.5f * (Zk.x + Zn.x), 0.5f * (Zk.y - Zn.y));
        out1[k] = make_float2(0.5f * (Zk.y + Zn.y), -0.5f * (Zk.x - Zn.x));
    }
}

// Convolution: one block per (batch-pair, channel). z = x[b0] + i*x[b1].
__global__ void __launch_bounds__(NT) ker_conv(const float* __restrict__ x, float* __restrict__ o) {
    extern __shared__ float2 sm[];
    float2* A = sm;
    float2* B = sm + N_FFT;
    const int blk = blockIdx.x;       // 0..1023
    const int d = blk & (D_CH - 1);
    const int pr = blk >> 9;          // batch pair 0 -> (0,1), 1 -> (2,3)
    const int tid = threadIdx.x;
    const float* x0 = x + (size_t)(2 * pr) * SEQ * D_CH + d;
    const float* x1 = x0 + (size_t)SEQ * D_CH;
    for (int j = tid; j < SEQ; j += NT)
        A[j] = make_float2(x0[(size_t)j * D_CH], x1[(size_t)j * D_CH]);
    for (int j = SEQ + tid; j < N_FFT; j += NT)
        A[j] = make_float2(0.0f, 0.0f);
    __syncthreads();

    fft8192<false>(A, B, tid);  // result in B

    const float2* tf = g_tfft + (size_t)d * N_FFT;
    const float inv = 1.0f / (float)N_FFT;
    for (int k = tid; k < N_FFT; k += NT) {
        float2 v = cmul(B[k], tf[k]);
        B[k] = make_float2(v.x * inv, v.y * inv);  // fold IFFT scale here
    }
    __syncthreads();

    fft8192<true>(B, A, tid);   // result in A

    float* o0 = o + (size_t)(2 * pr) * SEQ * D_CH + d;
    float* o1 = o0 + (size_t)SEQ * D_CH;
    for (int i = tid; i < SEQ; i += NT) {
        float2 v = A[i];
        o0[(size_t)i * D_CH] = v.x;
        o1[(size_t)i * D_CH] = v.y;
    }
}

extern "C" void kernel_launch(void* const* d_in, const int* in_sizes, int n_in,
                              void* d_out, int out_size) {
    const float* x = (const float*)d_in[0];
    const float* t = (const float*)d_in[1];
    // Safety: x has 8388608 elements, t has 4194304. Swap if the registry orders differently.
    if (n_in >= 2 && in_sizes[0] < in_sizes[1]) {
        const float* tmp = x; x = t; t = tmp;
    }
    float* o = (float*)d_out;

    const size_t smem = 2 * (size_t)N_FFT * sizeof(float2);  // 128 KB
    cudaFuncSetAttribute(ker_tfft, cudaFuncAttributeMaxDynamicSharedMemorySize, (int)smem);
    cudaFuncSetAttribute(ker_conv, cudaFuncAttributeMaxDynamicSharedMemorySize, (int)smem);

    ker_tw<<<(N_FFT + 255) / 256, 256>>>();
    ker_tfft<<<D_CH / 2, NT, smem>>>(t);
    ker_conv<<<2 * D_CH, NT, smem>>>(x, o);
}

// round 2
// speedup vs baseline: 1.3813x; 1.3813x over previous
#include <cuda_runtime.h>
#include <cstdint>

#define N_FFT 8192
#define NT    512
#define D_CH  512
#define SEQ   4096
#define NBATCH 4

// Padded smem index: +1 float2 every 16 -> kills power-of-2 stride bank conflicts
#define PADI(i) ((i) + ((i) >> 4))
#define BUFSZ (N_FFT + (N_FFT >> 4))   // 8704 float2 per buffer

// Scratch (allowed: __device__ globals, no runtime allocation)
__device__ float2 g_tw[N_FFT];                          // twiddle table exp(-2*pi*i*k/N)
__device__ float2 g_tfft[(size_t)D_CH * N_FFT];         // per-channel spectrum of t (33.5 MB)
__device__ float  g_xT[(size_t)NBATCH * D_CH * SEQ];    // x transposed (b, d, n) 33.5 MB
__device__ float  g_tT[(size_t)D_CH * 2 * SEQ];         // t transposed (d, 2n)   16.8 MB
__device__ float  g_oT[(size_t)NBATCH * D_CH * SEQ];    // o transposed (b, d, n) 33.5 MB

__device__ __forceinline__ float2 cadd(float2 a, float2 b) { return make_float2(a.x + b.x, a.y + b.y); }
__device__ __forceinline__ float2 csub(float2 a, float2 b) { return make_float2(a.x - b.x, a.y - b.y); }
__device__ __forceinline__ float2 cmul(float2 a, float2 b) {
    return make_float2(a.x * b.x - a.y * b.y, a.x * b.y + a.y * b.x);
}

template <bool INV>
__device__ __forceinline__ float2 mulJ(float2 z) {
    return INV ? make_float2(-z.y, z.x) : make_float2(z.y, -z.x);
}
template <bool INV>
__device__ __forceinline__ float2 mulW81(float2 z) {
    const float c = 0.70710678118654752440f;
    return INV ? make_float2(c * (z.x - z.y), c * (z.x + z.y))
               : make_float2(c * (z.x + z.y), c * (z.y - z.x));
}
template <bool INV>
__device__ __forceinline__ float2 mulW83(float2 z) {
    const float c = 0.70710678118654752440f;
    return INV ? make_float2(-c * (z.x + z.y), c * (z.x - z.y))
               : make_float2(c * (z.y - z.x), -c * (z.x + z.y));
}

template <bool INV>
__device__ __forceinline__ void dft8(const float2 a[8], float2 y[8]) {
    float2 b0 = cadd(a[0], a[4]), b1 = cadd(a[1], a[5]), b2 = cadd(a[2], a[6]), b3 = cadd(a[3], a[7]);
    float2 c0 = csub(a[0], a[4]), c1 = csub(a[1], a[5]), c2 = csub(a[2], a[6]), c3 = csub(a[3], a[7]);
    float2 d0 = cadd(b0, b2), d1 = csub(b0, b2), d2 = cadd(b1, b3), d3 = csub(b1, b3);
    y[0] = cadd(d0, d2);
    y[4] = csub(d0, d2);
    float2 jd3 = mulJ<INV>(d3);
    y[2] = cadd(d1, jd3);
    y[6] = csub(d1, jd3);
    float2 e0 = c0;
    float2 e1 = mulW81<INV>(c1);
    float2 e2 = mulJ<INV>(c2);
    float2 e3 = mulW83<INV>(c3);
    float2 f0 = cadd(e0, e2), f1 = csub(e0, e2), f2 = cadd(e1, e3), f3 = csub(e1, e3);
    y[1] = cadd(f0, f2);
    y[5] = csub(f0, f2);
    float2 jf3 = mulJ<INV>(f3);
    y[3] = cadd(f1, jf3);
    y[7] = csub(f1, jf3);
}

// One Stockham radix-8 pass (padded smem). X -> Y.
template <bool INV>
__device__ __forceinline__ void pass8(const float2* __restrict__ X, float2* __restrict__ Y,
                                      int sLog, int tid) {
    const int s = 1 << sLog;
    const int m = N_FFT >> (3 + sLog);
#pragma unroll
    for (int bi = tid; bi < N_FFT / 8; bi += NT) {
        const int q = bi & (s - 1);
        const int p = bi >> sLog;
        float2 a[8];
#pragma unroll
        for (int r = 0; r < 8; r++) a[r] = X[PADI(q + s * (p + r * m))];
        float2 y[8];
        dft8<INV>(a, y);
        const int base = p << sLog;
#pragma unroll
        for (int r = 1; r < 8; r++) {
            float2 w = g_tw[r * base];
            if (INV) w.y = -w.y;
            y[r] = cmul(y[r], w);
        }
        const int ob = q + (p << (sLog + 3));
#pragma unroll
        for (int r = 0; r < 8; r++) Y[PADI(ob + s * r)] = y[r];
    }
}

__device__ __forceinline__ void pass2(const float2* __restrict__ X, float2* __restrict__ Y, int tid) {
#pragma unroll
    for (int q = tid; q < N_FFT / 2; q += NT) {
        float2 a = X[PADI(q)], b = X[PADI(q + N_FFT / 2)];
        Y[PADI(q)] = cadd(a, b);
        Y[PADI(q + N_FFT / 2)] = csub(a, b);
    }
}

// Full 8192-point FFT: input in A, result ends in B. Caller syncs before entry.
template <bool INV>
__device__ __forceinline__ void fft8192(float2* A, float2* B, int tid) {
    pass8<INV>(A, B, 0, tid); __syncthreads();
    pass8<INV>(B, A, 3, tid); __syncthreads();
    pass8<INV>(A, B, 6, tid); __syncthreads();
    pass8<INV>(B, A, 9, tid); __syncthreads();
    pass2(A, B, tid);         __syncthreads();
}

// ---------------------------------------------------------------------------
__global__ void ker_tw() {
    int k = blockIdx.x * blockDim.x + threadIdx.x;
    if (k < N_FFT) {
        float s, c;
        sincospif(-2.0f * (float)k / (float)N_FFT, &s, &c);
        g_tw[k] = make_float2(c, s);
    }
}

// Tiled transpose: in[b][r][c] -> out[b][c][r].  block (32,8), grid (C/32, R/32, B)
__global__ void __launch_bounds__(256) ker_T(const float* __restrict__ in, float* __restrict__ out,
                                             int R, int C) {
    __shared__ float tile[32][33];
    const size_t boff = (size_t)blockIdx.z * R * C;
    const float* I = in + boff;
    float* O = out + boff;
    const int c0 = blockIdx.x * 32, r0 = blockIdx.y * 32;
    const int cx = c0 + threadIdx.x;
#pragma unroll
    for (int i = threadIdx.y; i < 32; i += 8)
        tile[i][threadIdx.x] = I[(size_t)(r0 + i) * C + cx];
    __syncthreads();
    const int rx = r0 + threadIdx.x;
#pragma unroll
    for (int i = threadIdx.y; i < 32; i += 8)
        O[(size_t)(c0 + i) * R + rx] = tile[threadIdx.x][i];
}

// t spectrum: block handles channels (2c, 2c+1) as real+imag of one FFT. Reads g_tT (coalesced).
__global__ void __launch_bounds__(NT) ker_tfft() {
    extern __shared__ float2 sm[];
    float2* A = sm;
    float2* B = sm + BUFSZ;
    const int c0 = blockIdx.x;  // 0..255
    const int tid = threadIdx.x;
    const float* t0 = g_tT + (size_t)(2 * c0) * N_FFT;
    const float* t1 = t0 + N_FFT;
#pragma unroll
    for (int j4 = tid; j4 < N_FFT / 4; j4 += NT) {
        float4 u = *reinterpret_cast<const float4*>(t0 + 4 * j4);
        float4 v = *reinterpret_cast<const float4*>(t1 + 4 * j4);
        A[PADI(4 * j4 + 0)] = make_float2(u.x, v.x);
        A[PADI(4 * j4 + 1)] = make_float2(u.y, v.y);
        A[PADI(4 * j4 + 2)] = make_float2(u.z, v.z);
        A[PADI(4 * j4 + 3)] = make_float2(u.w, v.w);
    }
    __syncthreads();
    fft8192<false>(A, B, tid);
    float2* out0 = g_tfft + (size_t)(2 * c0) * N_FFT;
    float2* out1 = g_tfft + (size_t)(2 * c0 + 1) * N_FFT;
    for (int k = tid; k < N_FFT; k += NT) {
        float2 Zk = B[PADI(k)];
        float2 Zn = B[PADI((N_FFT - k) & (N_FFT - 1))];
        out0[k] = make_float2(0.5f * (Zk.x + Zn.x), 0.5f * (Zk.y - Zn.y));
        out1[k] = make_float2(0.5f * (Zk.y + Zn.y), -0.5f * (Zk.x - Zn.x));
    }
}

// Convolution: one block per (batch-pair, channel). z = x[b0] + i*x[b1]. All I/O coalesced.
__global__ void __launch_bounds__(NT) ker_conv() {
    extern __shared__ float2 sm[];
    float2* A = sm;
    float2* B = sm + BUFSZ;
    const int blk = blockIdx.x;       // 0..1023
    const int d = blk & (D_CH - 1);
    const int pr = blk >> 9;          // batch pair 0 -> (0,1), 1 -> (2,3)
    const int tid = threadIdx.x;
    const float* x0 = g_xT + ((size_t)(2 * pr) * D_CH + d) * SEQ;
    const float* x1 = x0 + (size_t)D_CH * SEQ;
#pragma unroll
    for (int j4 = tid; j4 < SEQ / 4; j4 += NT) {
        float4 u = *reinterpret_cast<const float4*>(x0 + 4 * j4);
        float4 v = *reinterpret_cast<const float4*>(x1 + 4 * j4);
        A[PADI(4 * j4 + 0)] = make_float2(u.x, v.x);
        A[PADI(4 * j4 + 1)] = make_float2(u.y, v.y);
        A[PADI(4 * j4 + 2)] = make_float2(u.z, v.z);
        A[PADI(4 * j4 + 3)] = make_float2(u.w, v.w);
    }
    for (int j = SEQ + tid; j < N_FFT; j += NT)
        A[PADI(j)] = make_float2(0.0f, 0.0f);
    __syncthreads();

    fft8192<false>(A, B, tid);  // result in B

    const float2* tf = g_tfft + (size_t)d * N_FFT;
    const float inv = 1.0f / (float)N_FFT;
    for (int k = tid; k < N_FFT; k += NT) {
        float2 v = cmul(B[PADI(k)], tf[k]);
        B[PADI(k)] = make_float2(v.x * inv, v.y * inv);  // fold IFFT scale
    }
    __syncthreads();

    fft8192<true>(B, A, tid);   // result in A

    float* o0 = g_oT + ((size_t)(2 * pr) * D_CH + d) * SEQ;
    float* o1 = o0 + (size_t)D_CH * SEQ;
#pragma unroll
    for (int j4 = tid; j4 < SEQ / 4; j4 += NT) {
        float2 a0 = A[PADI(4 * j4 + 0)];
        float2 a1 = A[PADI(4 * j4 + 1)];
        float2 a2 = A[PADI(4 * j4 + 2)];
        float2 a3 = A[PADI(4 * j4 + 3)];
        *reinterpret_cast<float4*>(o0 + 4 * j4) = make_float4(a0.x, a1.x, a2.x, a3.x);
        *reinterpret_cast<float4*>(o1 + 4 * j4) = make_float4(a0.y, a1.y, a2.y, a3.y);
    }
}

extern "C" void kernel_launch(void* const* d_in, const int* in_sizes, int n_in,
                              void* d_out, int out_size) {
    const float* x = (const float*)d_in[0];
    const float* t = (const float*)d_in[1];
    if (n_in >= 2 && in_sizes[0] < in_sizes[1]) {
        const float* tmp = x; x = t; t = tmp;
    }
    float* o = (float*)d_out;

    float* xT;  cudaGetSymbolAddress((void**)&xT, g_xT);
    float* tT;  cudaGetSymbolAddress((void**)&tT, g_tT);
    float* oT;  cudaGetSymbolAddress((void**)&oT, g_oT);

    const size_t smem = 2 * (size_t)BUFSZ * sizeof(float2);  // 139264 B
    cudaFuncSetAttribute(ker_tfft, cudaFuncAttributeMaxDynamicSharedMemorySize, (int)smem);
    cudaFuncSetAttribute(ker_conv, cudaFuncAttributeMaxDynamicSharedMemorySize, (int)smem);

    ker_tw<<<(N_FFT + 255) / 256, 256>>>();

    // Transposes: x (4,4096,512) -> xT (4,512,4096); t (8192,512) -> tT (512,8192)
    {
        dim3 blk(32, 8);
        dim3 gx(D_CH / 32, SEQ / 32, NBATCH);
        ker_T<<<gx, blk>>>(x, xT, SEQ, D_CH);
        dim3 gt(D_CH / 32, (2 * SEQ) / 32, 1);
        ker_T<<<gt, blk>>>(t, tT, 2 * SEQ, D_CH);
    }

    ker_tfft<<<D_CH / 2, NT, smem>>>();
    ker_conv<<<2 * D_CH, NT, smem>>>();

    // oT (4,512,4096) -> o (4,4096,512)
    {
        dim3 blk(32, 8);
        dim3 go(SEQ / 32, D_CH / 32, NBATCH);
        ker_T<<<go, blk>>>(oT, o, D_CH, SEQ);
    }
}